// round 6
// baseline (speedup 1.0000x reference)
#include <cuda_runtime.h>
#include <cuda_bf16.h>

// Problem constants (fixed by the dataset)
#define MAXN 50000
#define CAP  128      // max in-degree capacity (Poisson(16): P(deg>=128) ~ 0)

// Scratch (device globals: allocation-free per harness rules)
__device__ __align__(128) int   g_cnt[MAXN];                // in-degree
__device__ __align__(128) int   g_slot[(size_t)MAXN * CAP]; // bucketed src per dst
__device__ __align__(128) float g_z  [(size_t)MAXN * 128];  // z  = x @ W1
__device__ __align__(128) float g_h2 [(size_t)MAXN * 128];  // relu(gather(z)+b1)*mask
__device__ __align__(128) float g_t  [(size_t)MAXN * 16];   // t  = h2 @ W2
__device__ int g_is64;                                      // edge dtype flag

// ---------------------------------------------------------------------------
__global__ void zero_cnt_kernel(int n) {
    int tid = blockIdx.x * blockDim.x + threadIdx.x;
    if (tid == 0) g_is64 = 1;
    for (int i = tid; i < n; i += gridDim.x * blockDim.x)
        g_cnt[i] = 0;
}

// Probe: decide whether the edge buffer is int64 or int32.
// If data is int32, int64-interpretation of a src entry = lo + hi*2^32 with hi
// a random node id -> out of [0,n) with overwhelming probability.
__global__ void probe_kernel(const void* __restrict__ ei, int E, int n) {
    const long long* e64 = (const long long*)ei;
    int i = threadIdx.x;
    int m = min(128, E);
    if (i < m) {
        long long v = e64[i];          // within allocation for either dtype
        if (v < 0 || v >= (long long)n) atomicAnd(&g_is64, 0);
    }
}

// Build dst-bucketed adjacency: pos = cnt[dst]++, slot[dst*CAP+pos] = src
__global__ void build_kernel(const void* __restrict__ ei, int E, int n) {
    int e = blockIdx.x * blockDim.x + threadIdx.x;
    if (e >= E) return;
    int s, d;
    if (g_is64) {
        const long long* e64 = (const long long*)ei;
        s = (int)e64[e];
        d = (int)e64[(size_t)E + e];
    } else {
        const int* e32 = (const int*)ei;
        s = e32[e];
        d = e32[(size_t)E + e];
    }
    if (d < 0 || d >= n || s < 0 || s >= n) return;
    int pos = atomicAdd(&g_cnt[d], 1);
    if (pos < CAP) g_slot[(size_t)d * CAP + pos] = s;
}

// ---------------------------------------------------------------------------
// GEMM1: g_z[N,128] = X[N,128] @ W1[128,128]  (fp32 SIMT, 64x128 tile / block)
__global__ __launch_bounds__(256) void gemm1_kernel(
    const float* __restrict__ X, const float* __restrict__ W, int n) {
    __shared__ float As[16][68];    // transposed x tile  [k][row]
    __shared__ float Bs[16][128];   // W1 tile            [k][col]
    const int tid  = threadIdx.x;
    const int row0 = blockIdx.x * 64;
    const int tr = tid >> 5;        // 0..7  (8 rows each)
    const int tc = tid & 31;        // 0..31 (4 cols each)

    float acc[8][4];
#pragma unroll
    for (int r = 0; r < 8; r++)
#pragma unroll
        for (int c = 0; c < 4; c++) acc[r][c] = 0.f;

    const int lr = tid >> 2;            // 0..63 (A-tile row)
    const int lc = (tid & 3) << 2;      // 0,4,8,12
    int gr_a = row0 + lr; if (gr_a >= n) gr_a = n - 1;  // clamp (store guarded)
    const int bi = tid * 8;             // B-tile element base
    const int bk = bi >> 7, bc = bi & 127;

    for (int k0 = 0; k0 < 128; k0 += 16) {
        float4 av = *(const float4*)(X + (size_t)gr_a * 128 + k0 + lc);
        As[lc + 0][lr] = av.x; As[lc + 1][lr] = av.y;
        As[lc + 2][lr] = av.z; As[lc + 3][lr] = av.w;

        float4 b0 = *(const float4*)(W + (size_t)(k0 + bk) * 128 + bc);
        float4 b1v = *(const float4*)(W + (size_t)(k0 + bk) * 128 + bc + 4);
        *(float4*)&Bs[bk][bc]     = b0;   // Bs row stride 512B: 16B aligned
        *(float4*)&Bs[bk][bc + 4] = b1v;
        __syncthreads();

#pragma unroll
        for (int kk = 0; kk < 16; kk++) {
            float4 b = *(const float4*)&Bs[kk][tc * 4];
            float a[8];
#pragma unroll
            for (int r = 0; r < 8; r++) a[r] = As[kk][tr * 8 + r];
#pragma unroll
            for (int r = 0; r < 8; r++) {
                acc[r][0] = fmaf(a[r], b.x, acc[r][0]);
                acc[r][1] = fmaf(a[r], b.y, acc[r][1]);
                acc[r][2] = fmaf(a[r], b.z, acc[r][2]);
                acc[r][3] = fmaf(a[r], b.w, acc[r][3]);
            }
        }
        __syncthreads();
    }
#pragma unroll
    for (int r = 0; r < 8; r++) {
        int gr = row0 + tr * 8 + r;
        if (gr < n) {
            float4 v = make_float4(acc[r][0], acc[r][1], acc[r][2], acc[r][3]);
            *(float4*)(g_z + (size_t)gr * 128 + tc * 4) = v;
        }
    }
}

// ---------------------------------------------------------------------------
// Gather1: h2[i] = relu( mean_{s in nbr(i)} z[s] + b1 ) * mask[i]
// One warp per node, one float4 (4 cols) per lane.
__global__ __launch_bounds__(256) void gather1_kernel(
    const float* __restrict__ b1, const float* __restrict__ mask, int n) {
    const int warp = (blockIdx.x * blockDim.x + threadIdx.x) >> 5;
    const int lane = threadIdx.x & 31;
    if (warp >= n) return;

    const int deg = g_cnt[warp];
    const int d   = min(deg, CAP);
    const int* sl = g_slot + (size_t)warp * CAP;
    float4 acc = make_float4(0.f, 0.f, 0.f, 0.f);

    for (int base = 0; base < d; base += 32) {
        int nn = min(32, d - base);
        int my = (lane < nn) ? sl[base + lane] : 0;
        int e = 0;
        for (; e + 4 <= nn; e += 4) {   // 4-way MLP
            int s0 = __shfl_sync(0xffffffffu, my, e + 0);
            int s1 = __shfl_sync(0xffffffffu, my, e + 1);
            int s2 = __shfl_sync(0xffffffffu, my, e + 2);
            int s3 = __shfl_sync(0xffffffffu, my, e + 3);
            float4 v0 = *(const float4*)(g_z + (size_t)s0 * 128 + lane * 4);
            float4 v1 = *(const float4*)(g_z + (size_t)s1 * 128 + lane * 4);
            float4 v2 = *(const float4*)(g_z + (size_t)s2 * 128 + lane * 4);
            float4 v3 = *(const float4*)(g_z + (size_t)s3 * 128 + lane * 4);
            acc.x += v0.x + v1.x + v2.x + v3.x;
            acc.y += v0.y + v1.y + v2.y + v3.y;
            acc.z += v0.z + v1.z + v2.z + v3.z;
            acc.w += v0.w + v1.w + v2.w + v3.w;
        }
        for (; e < nn; e++) {
            int s = __shfl_sync(0xffffffffu, my, e);
            float4 v = *(const float4*)(g_z + (size_t)s * 128 + lane * 4);
            acc.x += v.x; acc.y += v.y; acc.z += v.z; acc.w += v.w;
        }
    }
    float scale = 1.f / (float)max(deg, 1);
    float bb0 = b1[lane * 4 + 0], bb1 = b1[lane * 4 + 1];
    float bb2 = b1[lane * 4 + 2], bb3 = b1[lane * 4 + 3];
    const float* mp = mask + (size_t)warp * 128 + lane * 4;
    float m0 = mp[0], m1 = mp[1], m2 = mp[2], m3 = mp[3];
    float4 r;
    r.x = fmaxf(fmaf(acc.x, scale, bb0), 0.f) * m0;
    r.y = fmaxf(fmaf(acc.y, scale, bb1), 0.f) * m1;
    r.z = fmaxf(fmaf(acc.z, scale, bb2), 0.f) * m2;
    r.w = fmaxf(fmaf(acc.w, scale, bb3), 0.f) * m3;
    *(float4*)(g_h2 + (size_t)warp * 128 + lane * 4) = r;
}

// ---------------------------------------------------------------------------
// GEMM2: g_t[N,16] = h2[N,128] @ W2[128,16]  (no bias; added after gather2)
__global__ __launch_bounds__(256) void gemm2_kernel(
    const float* __restrict__ W2, int n) {
    __shared__ float Hs[64][129];   // +1 pad: conflict-free column reads
    __shared__ float W2s[128][16];
    const int tid  = threadIdx.x;
    const int row0 = blockIdx.x * 64;

    {   // load W2 (2048 floats, 8 per thread) — scalar, alignment-safe
        int i = tid * 8;
        int k = i >> 4, c = i & 15;
#pragma unroll
        for (int j = 0; j < 8; j++) W2s[k][c + j] = W2[i + j];
    }
#pragma unroll
    for (int it = 0; it < 8; it++) {   // load 64x128 h2 tile
        int idx = (it * 256 + tid) * 4;
        int r = idx >> 7, c = idx & 127;
        int gr = row0 + r;
        float4 v = (gr < n) ? *(const float4*)(g_h2 + (size_t)gr * 128 + c)
                            : make_float4(0.f, 0.f, 0.f, 0.f);
        // scalar STS: Hs row stride is 516B, float4 STS would be misaligned
        Hs[r][c + 0] = v.x; Hs[r][c + 1] = v.y;
        Hs[r][c + 2] = v.z; Hs[r][c + 3] = v.w;
    }
    __syncthreads();

    const int r = tid >> 2;           // 0..63
    const int q = (tid & 3) * 4;      // 0,4,8,12
    float4 acc = make_float4(0.f, 0.f, 0.f, 0.f);
#pragma unroll
    for (int k = 0; k < 128; k++) {
        float a = Hs[r][k];
        acc.x = fmaf(a, W2s[k][q + 0], acc.x);
        acc.y = fmaf(a, W2s[k][q + 1], acc.y);
        acc.z = fmaf(a, W2s[k][q + 2], acc.z);
        acc.w = fmaf(a, W2s[k][q + 3], acc.w);
    }
    int gr = row0 + r;
    if (gr < n) *(float4*)(g_t + (size_t)gr * 16 + q) = acc;
}

// ---------------------------------------------------------------------------
// Gather2: out[i] = mean_{s in nbr(i)} t[s] + b2   (4 lanes per node)
__global__ __launch_bounds__(256) void gather2_kernel(
    const float* __restrict__ b2, float* __restrict__ out, int n) {
    const int gid  = blockIdx.x * blockDim.x + threadIdx.x;
    const int node = gid >> 2;
    const int q    = (gid & 3) * 4;
    if (node >= n) return;

    const int deg = g_cnt[node];
    const int d   = min(deg, CAP);
    const int* sl = g_slot + (size_t)node * CAP;
    float4 acc = make_float4(0.f, 0.f, 0.f, 0.f);

    int e = 0;
    for (; e + 4 <= d; e += 4) {
        int s0 = sl[e], s1 = sl[e + 1], s2 = sl[e + 2], s3 = sl[e + 3];
        float4 v0 = *(const float4*)(g_t + (size_t)s0 * 16 + q);
        float4 v1 = *(const float4*)(g_t + (size_t)s1 * 16 + q);
        float4 v2 = *(const float4*)(g_t + (size_t)s2 * 16 + q);
        float4 v3 = *(const float4*)(g_t + (size_t)s3 * 16 + q);
        acc.x += v0.x + v1.x + v2.x + v3.x;
        acc.y += v0.y + v1.y + v2.y + v3.y;
        acc.z += v0.z + v1.z + v2.z + v3.z;
        acc.w += v0.w + v1.w + v2.w + v3.w;
    }
    for (; e < d; e++) {
        int s = sl[e];
        float4 v = *(const float4*)(g_t + (size_t)s * 16 + q);
        acc.x += v.x; acc.y += v.y; acc.z += v.z; acc.w += v.w;
    }
    float scale = 1.f / (float)max(deg, 1);
    out[(size_t)node * 16 + q + 0] = fmaf(acc.x, scale, b2[q + 0]);
    out[(size_t)node * 16 + q + 1] = fmaf(acc.y, scale, b2[q + 1]);
    out[(size_t)node * 16 + q + 2] = fmaf(acc.z, scale, b2[q + 2]);
    out[(size_t)node * 16 + q + 3] = fmaf(acc.w, scale, b2[q + 3]);
}

// ---------------------------------------------------------------------------
extern "C" void kernel_launch(void* const* d_in, const int* in_sizes, int n_in,
                              void* d_out, int out_size) {
    const float* x    = (const float*)d_in[0];
    const void*  ei   = d_in[1];            // int32 or int64, probed on device
    const float* W1   = (const float*)d_in[2];
    const float* b1   = (const float*)d_in[3];
    const float* W2   = (const float*)d_in[4];
    const float* b2   = (const float*)d_in[5];
    const float* mask = (const float*)d_in[6];
    float*       out  = (float*)d_out;

    int n = in_sizes[0] / 128;
    if (n > MAXN) n = MAXN;
    int E = in_sizes[1] / 2;

    zero_cnt_kernel<<<128, 512>>>(n);
    probe_kernel<<<1, 128>>>(ei, E, n);
    build_kernel<<<(E + 255) / 256, 256>>>(ei, E, n);
    gemm1_kernel<<<(n + 63) / 64, 256>>>(x, W1, n);
    gather1_kernel<<<(n + 7) / 8, 256>>>(b1, mask, n);
    gemm2_kernel<<<(n + 63) / 64, 256>>>(W2, n);
    gather2_kernel<<<(4 * n + 255) / 256, 256>>>(b2, out, n);
}

// round 11
// speedup vs baseline: 1.0826x; 1.0826x over previous
#include <cuda_runtime.h>
#include <cuda_bf16.h>
#include <cstdint>

// Problem constants (fixed by the dataset)
#define MAXN 50000
#define CAP  128      // max in-degree capacity (Poisson(16): P(deg>=128) ~ 0)

// Scratch (device globals: allocation-free per harness rules)
__device__ __align__(128) int   g_cnt[MAXN];                // in-degree
__device__ __align__(128) int   g_slot[(size_t)MAXN * CAP]; // bucketed src per dst
__device__ __align__(128) float g_z  [(size_t)MAXN * 128];  // z  = x @ W1
__device__ __align__(128) float g_h2 [(size_t)MAXN * 128];  // relu(gather(z)+b1)*mask
__device__ __align__(128) float g_t  [(size_t)MAXN * 16];   // t  = h2 @ W2
__device__ int g_is64;                                      // edge dtype flag

// ---------------------------------------------------------------------------
__device__ __forceinline__ uint32_t smem_to_u32(const void* p) {
    uint32_t a;
    asm("{ .reg .u64 t; cvta.to.shared.u64 t, %1; cvt.u32.u64 %0, t; }"
        : "=r"(a) : "l"(p));
    return a;
}

// Portable tensor-core primitives (sm_80+; valid on base compute_103 target)
#define LDSM_X4(r, addr) \
    asm volatile("ldmatrix.sync.aligned.m8n8.x4.shared.b16 {%0,%1,%2,%3}, [%4];" \
        : "=r"((r)[0]), "=r"((r)[1]), "=r"((r)[2]), "=r"((r)[3]) : "r"(addr))

#define MMA_BF16(d, a, b) \
    asm volatile("mma.sync.aligned.m16n8k16.row.col.f32.bf16.bf16.f32 " \
        "{%0,%1,%2,%3}, {%4,%5,%6,%7}, {%8,%9}, {%0,%1,%2,%3};" \
        : "+f"((d)[0]), "+f"((d)[1]), "+f"((d)[2]), "+f"((d)[3]) \
        : "r"((a)[0]), "r"((a)[1]), "r"((a)[2]), "r"((a)[3]), \
          "r"((b)[0]), "r"((b)[1]))

// ---------------------------------------------------------------------------
__global__ void zero_cnt_kernel(int n) {
    int tid = blockIdx.x * blockDim.x + threadIdx.x;
    if (tid == 0) g_is64 = 1;
    for (int i = tid; i < n; i += gridDim.x * blockDim.x)
        g_cnt[i] = 0;
}

// Probe: decide whether the edge buffer is int64 or int32 (see R4 notes).
__global__ void probe_kernel(const void* __restrict__ ei, int E, int n) {
    const long long* e64 = (const long long*)ei;
    int i = threadIdx.x;
    int m = min(128, E);
    if (i < m) {
        long long v = e64[i];
        if (v < 0 || v >= (long long)n) atomicAnd(&g_is64, 0);
    }
}

// Build dst-bucketed adjacency: pos = cnt[dst]++, slot[dst*CAP+pos] = src
__global__ void build_kernel(const void* __restrict__ ei, int E, int n) {
    int e = blockIdx.x * blockDim.x + threadIdx.x;
    if (e >= E) return;
    int s, d;
    if (g_is64) {
        const long long* e64 = (const long long*)ei;
        s = (int)e64[e];
        d = (int)e64[(size_t)E + e];
    } else {
        const int* e32 = (const int*)ei;
        s = e32[e];
        d = e32[(size_t)E + e];
    }
    if (d < 0 || d >= n || s < 0 || s >= n) return;
    int pos = atomicAdd(&g_cnt[d], 1);
    if (pos < CAP) g_slot[(size_t)d * CAP + pos] = s;
}

// ============================================================================
// GEMM1 (HMMA via mma.sync): g_z[N,128] = X[N,128] @ W1[128,128]
//   Split-bf16, 3 passes: Ah*Bh + Ah*Bl + Al*Bh  (fp32 accumulators).
//   Per block: 128 rows x 128 cols, 8 warps each own a 16-row strip.
//   smem tiles: bf16, row stride 136 elems (272B == 16 mod 128 -> ldmatrix
//   conflict-free, 16B aligned).
// ============================================================================
#define XS 136
#define TILE_ELEMS (128 * XS)
#define G1_SMEM_TOTAL (4 * TILE_ELEMS * 2)   // Xh, Xl, Bh, Bl = 139264 B

__global__ void __launch_bounds__(256, 1)
gemm1_mma_kernel(const float* __restrict__ X, const float* __restrict__ W, int n) {
    extern __shared__ __align__(16) char smem_raw[];
    __nv_bfloat16* Xh = (__nv_bfloat16*)smem_raw;       // [128][XS] row=m, col=k
    __nv_bfloat16* Xl = Xh + TILE_ELEMS;
    __nv_bfloat16* Bh = Xl + TILE_ELEMS;                // [128][XS] row=n, col=k (W^T)
    __nv_bfloat16* Bl = Bh + TILE_ELEMS;

    const int tid  = threadIdx.x;
    const int wid  = tid >> 5;
    const int lane = tid & 31;
    const int row0 = blockIdx.x * 128;

    // ---- stage + split-convert X tile: thread -> (row, k-half) ----
    {
        const int r = tid >> 1, half = tid & 1;
        int gr = row0 + r; if (gr >= n) gr = n - 1;   // clamp; stores guarded later
        const float* xp = X + (size_t)gr * 128 + half * 64;
        __nv_bfloat16* ph = Xh + r * XS + half * 64;
        __nv_bfloat16* pl = Xl + r * XS + half * 64;
#pragma unroll
        for (int j = 0; j < 64; j += 4) {
            float4 v = *(const float4*)(xp + j);
            float fv[4] = {v.x, v.y, v.z, v.w};
#pragma unroll
            for (int e = 0; e < 4; e++) {
                __nv_bfloat16 h = __float2bfloat16(fv[e]);
                __nv_bfloat16 l = __float2bfloat16(fv[e] - __bfloat162float(h));
                ph[j + e] = h;
                pl[j + e] = l;
            }
        }
    }
    // ---- stage + split-convert W^T: Bh/Bl[nc][k] = split(W[k][nc]) ----
    {
        const int nc = tid >> 1, half = tid & 1;
        __nv_bfloat16* ph = Bh + nc * XS + half * 64;
        __nv_bfloat16* pl = Bl + nc * XS + half * 64;
#pragma unroll 8
        for (int j = 0; j < 64; j++) {
            int k = half * 64 + j;
            float f = W[(size_t)k * 128 + nc];
            __nv_bfloat16 h = __float2bfloat16(f);
            __nv_bfloat16 l = __float2bfloat16(f - __bfloat162float(h));
            ph[j] = h;
            pl[j] = l;
        }
    }
    __syncthreads();

    // ---- warp-tile mma: warp 'wid' computes rows [wid*16, wid*16+16) ----
    float acc[16][4];
#pragma unroll
    for (int nf = 0; nf < 16; nf++)
#pragma unroll
        for (int c = 0; c < 4; c++) acc[nf][c] = 0.f;

    // A ldmatrix.x4 lane address: mat0 rows0-7 k0-7 | mat1 rows8-15 k0-7 |
    //                             mat2 rows0-7 k8-15 | mat3 rows8-15 k8-15
    const int a_row  = wid * 16 + ((lane >> 3) & 1) * 8 + (lane & 7);
    const int a_koff = (lane >> 4) * 8;
    const uint32_t a_hi_base = smem_to_u32(Xh + a_row * XS + a_koff);
    const uint32_t a_lo_base = smem_to_u32(Xl + a_row * XS + a_koff);

    // Fused B ldmatrix.x4: lanes 0-15 address Bh (k0 / k8), lanes 16-31 Bl.
    // Result regs: r0,r1 = Bh-frag (b0,b1), r2,r3 = Bl-frag.
    {
        const __nv_bfloat16* barr = (lane & 16) ? Bl : Bh;
        const int b_row  = lane & 7;
        const int b_koff = ((lane >> 3) & 1) * 8;
        const uint32_t b_base = smem_to_u32(barr + b_row * XS + b_koff);

#pragma unroll
        for (int k = 0; k < 8; k++) {
            uint32_t ah[4], al[4];
            LDSM_X4(ah, a_hi_base + k * 32);   // 16 bf16 = 32B per k-step
            LDSM_X4(al, a_lo_base + k * 32);
#pragma unroll
            for (int nf = 0; nf < 16; nf++) {
                uint32_t bb[4];
                LDSM_X4(bb, b_base + nf * (8 * XS * 2) + k * 32);
                MMA_BF16(acc[nf], ah, bb + 0);   // Ah * Bh
                MMA_BF16(acc[nf], ah, bb + 2);   // Ah * Bl
                MMA_BF16(acc[nf], al, bb + 0);   // Al * Bh
            }
        }
    }

    // ---- epilogue: c0,c1 -> (row, col..col+1); c2,c3 -> (row+8, ..) ----
    {
        const int row_lo = row0 + wid * 16 + (lane >> 2);
        const int col    = (lane & 3) * 2;
#pragma unroll
        for (int nf = 0; nf < 16; nf++) {
            int c = nf * 8 + col;
            if (row_lo < n)
                *(float2*)(g_z + (size_t)row_lo * 128 + c) =
                    make_float2(acc[nf][0], acc[nf][1]);
            if (row_lo + 8 < n)
                *(float2*)(g_z + (size_t)(row_lo + 8) * 128 + c) =
                    make_float2(acc[nf][2], acc[nf][3]);
        }
    }
}

// ---------------------------------------------------------------------------
// Gather1: h2[i] = relu( mean_{s in nbr(i)} z[s] + b1 ) * mask[i]
__global__ __launch_bounds__(256) void gather1_kernel(
    const float* __restrict__ b1, const float* __restrict__ mask, int n) {
    const int warp = (blockIdx.x * blockDim.x + threadIdx.x) >> 5;
    const int lane = threadIdx.x & 31;
    if (warp >= n) return;

    const int deg = g_cnt[warp];
    const int d   = min(deg, CAP);
    const int* sl = g_slot + (size_t)warp * CAP;
    float4 acc = make_float4(0.f, 0.f, 0.f, 0.f);

    for (int base = 0; base < d; base += 32) {
        int nn = min(32, d - base);
        int my = (lane < nn) ? sl[base + lane] : 0;
        int e = 0;
        for (; e + 4 <= nn; e += 4) {   // 4-way MLP
            int s0 = __shfl_sync(0xffffffffu, my, e + 0);
            int s1 = __shfl_sync(0xffffffffu, my, e + 1);
            int s2 = __shfl_sync(0xffffffffu, my, e + 2);
            int s3 = __shfl_sync(0xffffffffu, my, e + 3);
            float4 v0 = *(const float4*)(g_z + (size_t)s0 * 128 + lane * 4);
            float4 v1 = *(const float4*)(g_z + (size_t)s1 * 128 + lane * 4);
            float4 v2 = *(const float4*)(g_z + (size_t)s2 * 128 + lane * 4);
            float4 v3 = *(const float4*)(g_z + (size_t)s3 * 128 + lane * 4);
            acc.x += v0.x + v1.x + v2.x + v3.x;
            acc.y += v0.y + v1.y + v2.y + v3.y;
            acc.z += v0.z + v1.z + v2.z + v3.z;
            acc.w += v0.w + v1.w + v2.w + v3.w;
        }
        for (; e < nn; e++) {
            int s = __shfl_sync(0xffffffffu, my, e);
            float4 v = *(const float4*)(g_z + (size_t)s * 128 + lane * 4);
            acc.x += v.x; acc.y += v.y; acc.z += v.z; acc.w += v.w;
        }
    }
    float scale = 1.f / (float)max(deg, 1);
    float bb0 = b1[lane * 4 + 0], bb1 = b1[lane * 4 + 1];
    float bb2 = b1[lane * 4 + 2], bb3 = b1[lane * 4 + 3];
    const float* mp = mask + (size_t)warp * 128 + lane * 4;
    float m0 = mp[0], m1 = mp[1], m2 = mp[2], m3 = mp[3];
    float4 r;
    r.x = fmaxf(fmaf(acc.x, scale, bb0), 0.f) * m0;
    r.y = fmaxf(fmaf(acc.y, scale, bb1), 0.f) * m1;
    r.z = fmaxf(fmaf(acc.z, scale, bb2), 0.f) * m2;
    r.w = fmaxf(fmaf(acc.w, scale, bb3), 0.f) * m3;
    *(float4*)(g_h2 + (size_t)warp * 128 + lane * 4) = r;
}

// ---------------------------------------------------------------------------
// GEMM2: g_t[N,16] = h2[N,128] @ W2[128,16]
__global__ __launch_bounds__(256) void gemm2_kernel(
    const float* __restrict__ W2, int n) {
    __shared__ float Hs[64][129];   // +1 pad: conflict-free column reads
    __shared__ float W2s[128][16];
    const int tid  = threadIdx.x;
    const int row0 = blockIdx.x * 64;

    {   // load W2 (2048 floats, 8 per thread) — scalar, alignment-safe
        int i = tid * 8;
        int k = i >> 4, c = i & 15;
#pragma unroll
        for (int j = 0; j < 8; j++) W2s[k][c + j] = W2[i + j];
    }
#pragma unroll
    for (int it = 0; it < 8; it++) {   // load 64x128 h2 tile
        int idx = (it * 256 + tid) * 4;
        int r = idx >> 7, c = idx & 127;
        int gr = row0 + r;
        float4 v = (gr < n) ? *(const float4*)(g_h2 + (size_t)gr * 128 + c)
                            : make_float4(0.f, 0.f, 0.f, 0.f);
        Hs[r][c + 0] = v.x; Hs[r][c + 1] = v.y;
        Hs[r][c + 2] = v.z; Hs[r][c + 3] = v.w;
    }
    __syncthreads();

    const int r = tid >> 2;           // 0..63
    const int q = (tid & 3) * 4;      // 0,4,8,12
    float4 acc = make_float4(0.f, 0.f, 0.f, 0.f);
#pragma unroll
    for (int k = 0; k < 128; k++) {
        float a = Hs[r][k];
        acc.x = fmaf(a, W2s[k][q + 0], acc.x);
        acc.y = fmaf(a, W2s[k][q + 1], acc.y);
        acc.z = fmaf(a, W2s[k][q + 2], acc.z);
        acc.w = fmaf(a, W2s[k][q + 3], acc.w);
    }
    int gr = row0 + r;
    if (gr < n) *(float4*)(g_t + (size_t)gr * 16 + q) = acc;
}

// ---------------------------------------------------------------------------
// Gather2: out[i] = mean_{s in nbr(i)} t[s] + b2   (4 lanes per node)
__global__ __launch_bounds__(256) void gather2_kernel(
    const float* __restrict__ b2, float* __restrict__ out, int n) {
    const int gid  = blockIdx.x * blockDim.x + threadIdx.x;
    const int node = gid >> 2;
    const int q    = (gid & 3) * 4;
    if (node >= n) return;

    const int deg = g_cnt[node];
    const int d   = min(deg, CAP);
    const int* sl = g_slot + (size_t)node * CAP;
    float4 acc = make_float4(0.f, 0.f, 0.f, 0.f);

    int e = 0;
    for (; e + 4 <= d; e += 4) {
        int s0 = sl[e], s1 = sl[e + 1], s2 = sl[e + 2], s3 = sl[e + 3];
        float4 v0 = *(const float4*)(g_t + (size_t)s0 * 16 + q);
        float4 v1 = *(const float4*)(g_t + (size_t)s1 * 16 + q);
        float4 v2 = *(const float4*)(g_t + (size_t)s2 * 16 + q);
        float4 v3 = *(const float4*)(g_t + (size_t)s3 * 16 + q);
        acc.x += v0.x + v1.x + v2.x + v3.x;
        acc.y += v0.y + v1.y + v2.y + v3.y;
        acc.z += v0.z + v1.z + v2.z + v3.z;
        acc.w += v0.w + v1.w + v2.w + v3.w;
    }
    for (; e < d; e++) {
        int s = sl[e];
        float4 v = *(const float4*)(g_t + (size_t)s * 16 + q);
        acc.x += v.x; acc.y += v.y; acc.z += v.z; acc.w += v.w;
    }
    float scale = 1.f / (float)max(deg, 1);
    out[(size_t)node * 16 + q + 0] = fmaf(acc.x, scale, b2[q + 0]);
    out[(size_t)node * 16 + q + 1] = fmaf(acc.y, scale, b2[q + 1]);
    out[(size_t)node * 16 + q + 2] = fmaf(acc.z, scale, b2[q + 2]);
    out[(size_t)node * 16 + q + 3] = fmaf(acc.w, scale, b2[q + 3]);
}

// ---------------------------------------------------------------------------
extern "C" void kernel_launch(void* const* d_in, const int* in_sizes, int n_in,
                              void* d_out, int out_size) {
    const float* x    = (const float*)d_in[0];
    const void*  ei   = d_in[1];            // int32 or int64, probed on device
    const float* W1   = (const float*)d_in[2];
    const float* b1   = (const float*)d_in[3];
    const float* W2   = (const float*)d_in[4];
    const float* b2   = (const float*)d_in[5];
    const float* mask = (const float*)d_in[6];
    float*       out  = (float*)d_out;

    int n = in_sizes[0] / 128;
    if (n > MAXN) n = MAXN;
    int E = in_sizes[1] / 2;

    // idempotent; persists on the function after the first (pre-capture) call
    cudaFuncSetAttribute(gemm1_mma_kernel,
                         cudaFuncAttributeMaxDynamicSharedMemorySize,
                         G1_SMEM_TOTAL);

    zero_cnt_kernel<<<128, 512>>>(n);
    probe_kernel<<<1, 128>>>(ei, E, n);
    build_kernel<<<(E + 255) / 256, 256>>>(ei, E, n);
    gemm1_mma_kernel<<<(n + 127) / 128, 256, G1_SMEM_TOTAL>>>(x, W1, n);
    gather1_kernel<<<(n + 7) / 8, 256>>>(b1, mask, n);
    gemm2_kernel<<<(n + 63) / 64, 256>>>(W2, n);
    gather2_kernel<<<(4 * n + 255) / 256, 256>>>(b2, out, n);
}

// round 12
// speedup vs baseline: 1.1417x; 1.0546x over previous
#include <cuda_runtime.h>
#include <cuda_bf16.h>
#include <cstdint>

// Problem constants (fixed by the dataset)
#define MAXN 50000
#define CAP  128      // max in-degree capacity (Poisson(16): P(deg>=128) ~ 0)

// Scratch (device globals: allocation-free per harness rules)
__device__ __align__(128) int   g_cnt[MAXN];                // in-degree
__device__ __align__(128) int   g_slot[(size_t)MAXN * CAP]; // bucketed src per dst
__device__ __align__(128) float g_z  [(size_t)MAXN * 128];  // z  = x @ W1
__device__ __align__(128) float g_t  [(size_t)MAXN * 16];   // t  = h2 @ W2
__device__ __align__(128) __nv_bfloat16 g_wh[128 * 128];    // W1^T hi  [nc][k]
__device__ __align__(128) __nv_bfloat16 g_wl[128 * 128];    // W1^T lo  [nc][k]
__device__ int g_is64;                                      // edge dtype flag

// ---------------------------------------------------------------------------
__device__ __forceinline__ uint32_t smem_to_u32(const void* p) {
    uint32_t a;
    asm("{ .reg .u64 t; cvta.to.shared.u64 t, %1; cvt.u32.u64 %0, t; }"
        : "=r"(a) : "l"(p));
    return a;
}

// Portable tensor-core primitives (sm_80+; valid on base compute_103 target)
#define LDSM_X4(r, addr) \
    asm volatile("ldmatrix.sync.aligned.m8n8.x4.shared.b16 {%0,%1,%2,%3}, [%4];" \
        : "=r"((r)[0]), "=r"((r)[1]), "=r"((r)[2]), "=r"((r)[3]) : "r"(addr))

#define MMA_BF16(d, a, b) \
    asm volatile("mma.sync.aligned.m16n8k16.row.col.f32.bf16.bf16.f32 " \
        "{%0,%1,%2,%3}, {%4,%5,%6,%7}, {%8,%9}, {%0,%1,%2,%3};" \
        : "+f"((d)[0]), "+f"((d)[1]), "+f"((d)[2]), "+f"((d)[3]) \
        : "r"((a)[0]), "r"((a)[1]), "r"((a)[2]), "r"((a)[3]), \
          "r"((b)[0]), "r"((b)[1]))

// ---------------------------------------------------------------------------
__global__ void zero_cnt_kernel(int n) {
    int tid = blockIdx.x * blockDim.x + threadIdx.x;
    if (tid == 0) g_is64 = 1;
    for (int i = tid; i < n; i += gridDim.x * blockDim.x)
        g_cnt[i] = 0;
}

// Probe: decide whether the edge buffer is int64 or int32 (see R4 notes).
__global__ void probe_kernel(const void* __restrict__ ei, int E, int n) {
    const long long* e64 = (const long long*)ei;
    int i = threadIdx.x;
    int m = min(128, E);
    if (i < m) {
        long long v = e64[i];
        if (v < 0 || v >= (long long)n) atomicAnd(&g_is64, 0);
    }
}

// Build dst-bucketed adjacency: pos = cnt[dst]++, slot[dst*CAP+pos] = src
__global__ void build_kernel(const void* __restrict__ ei, int E, int n) {
    int e = blockIdx.x * blockDim.x + threadIdx.x;
    if (e >= E) return;
    int s, d;
    if (g_is64) {
        const long long* e64 = (const long long*)ei;
        s = (int)e64[e];
        d = (int)e64[(size_t)E + e];
    } else {
        const int* e32 = (const int*)ei;
        s = e32[e];
        d = e32[(size_t)E + e];
    }
    if (d < 0 || d >= n || s < 0 || s >= n) return;
    int pos = atomicAdd(&g_cnt[d], 1);
    if (pos < CAP) g_slot[(size_t)d * CAP + pos] = s;
}

// One-time W1 split: g_wh/g_wl[nc][k] = split_bf16(W1[k][nc])
__global__ void prep_w_kernel(const float* __restrict__ W) {
    int i = blockIdx.x * blockDim.x + threadIdx.x;   // 16384
    int k = i >> 7, nc = i & 127;
    float f = W[i];                                  // W[k*128 + nc], coalesced
    __nv_bfloat16 h = __float2bfloat16(f);
    g_wh[nc * 128 + k] = h;
    g_wl[nc * 128 + k] = __float2bfloat16(f - __bfloat162float(h));
}

// ============================================================================
// GEMM1 (HMMA): g_z[N,128] = X[N,128] @ W1[128,128], split-bf16 (3 products).
//   Block: 512 threads / 16 warps, tile 128 rows x 128 cols.
//   Warp w: rows [(w>>1)*16, +16), col half (w&1)*64 -> nf=8 fragments.
//   smem rows stride XS=136 bf16 (272B == 16 mod 128: ldmatrix conflict-free).
// ============================================================================
#define XS 136
#define TILE_ELEMS (128 * XS)
#define G1_SMEM_TOTAL (4 * TILE_ELEMS * 2)   // Xh, Xl, Bh, Bl = 139264 B

__global__ void __launch_bounds__(512, 1)
gemm1_mma_kernel(const float* __restrict__ X, int n) {
    extern __shared__ __align__(16) char smem_raw[];
    __nv_bfloat16* Xh = (__nv_bfloat16*)smem_raw;       // [128][XS] row=m, col=k
    __nv_bfloat16* Xl = Xh + TILE_ELEMS;
    __nv_bfloat16* Bh = Xl + TILE_ELEMS;                // [128][XS] row=n, col=k
    __nv_bfloat16* Bl = Bh + TILE_ELEMS;

    const int tid  = threadIdx.x;
    const int wid  = tid >> 5;
    const int lane = tid & 31;
    const int row0 = blockIdx.x * 128;

    // ---- stage + split-convert X tile: thread -> (row, k-quarter) ----
    {
        const int r = tid >> 2, q = tid & 3;
        int gr = row0 + r; if (gr >= n) gr = n - 1;   // clamp; stores guarded later
        const float* xp = X + (size_t)gr * 128 + q * 32;
        __nv_bfloat16* ph = Xh + r * XS + q * 32;
        __nv_bfloat16* pl = Xl + r * XS + q * 32;
#pragma unroll
        for (int j = 0; j < 32; j += 4) {
            float4 v = *(const float4*)(xp + j);
            float fv[4] = {v.x, v.y, v.z, v.w};
#pragma unroll
            for (int e = 0; e < 4; e++) {
                __nv_bfloat16 h = __float2bfloat16(fv[e]);
                __nv_bfloat16 l = __float2bfloat16(fv[e] - __bfloat162float(h));
                ph[j + e] = h;
                pl[j + e] = l;
            }
        }
    }
    // ---- stage B tiles: straight uint4 copy from pre-split g_wh/g_wl ----
    {
#pragma unroll
        for (int it = 0; it < 4; it++) {
            int idx = tid + it * 512;          // 0..2047 : row = idx>>4, 16B chunk
            int row = idx >> 4, c16 = idx & 15;
            ((uint4*)(Bh + row * XS))[c16] = ((const uint4*)(g_wh + row * 128))[c16];
            ((uint4*)(Bl + row * XS))[c16] = ((const uint4*)(g_wl + row * 128))[c16];
        }
    }
    __syncthreads();

    // ---- warp tile: rows strip rs = (wid>>1)*16, col half ch = wid&1 ----
    const int rs = (wid >> 1) * 16;
    const int ch = wid & 1;

    float acc[8][4];
#pragma unroll
    for (int nf = 0; nf < 8; nf++)
#pragma unroll
        for (int c = 0; c < 4; c++) acc[nf][c] = 0.f;

    const int a_row  = rs + ((lane >> 3) & 1) * 8 + (lane & 7);
    const int a_koff = (lane >> 4) * 8;
    const uint32_t a_hi_base = smem_to_u32(Xh + a_row * XS + a_koff);
    const uint32_t a_lo_base = smem_to_u32(Xl + a_row * XS + a_koff);

    // Fused B ldmatrix.x4: lanes 0-15 -> Bh (k0/k8), lanes 16-31 -> Bl.
    {
        const __nv_bfloat16* barr = (lane & 16) ? Bl : Bh;
        const int b_row  = ch * 64 + (lane & 7);
        const int b_koff = ((lane >> 3) & 1) * 8;
        const uint32_t b_base = smem_to_u32(barr + b_row * XS + b_koff);

#pragma unroll
        for (int k = 0; k < 8; k++) {
            uint32_t ah[4], al[4];
            LDSM_X4(ah, a_hi_base + k * 32);   // 16 bf16 = 32B per k-step
            LDSM_X4(al, a_lo_base + k * 32);
#pragma unroll
            for (int nf = 0; nf < 8; nf++) {
                uint32_t bb[4];
                LDSM_X4(bb, b_base + nf * (8 * XS * 2) + k * 32);
                MMA_BF16(acc[nf], ah, bb + 0);   // Ah * Bh
                MMA_BF16(acc[nf], ah, bb + 2);   // Ah * Bl
                MMA_BF16(acc[nf], al, bb + 0);   // Al * Bh
            }
        }
    }

    // ---- epilogue: c0,c1 -> (row, col..col+1); c2,c3 -> (row+8, ..) ----
    {
        const int row_lo = row0 + rs + (lane >> 2);
        const int colb   = ch * 64 + (lane & 3) * 2;
#pragma unroll
        for (int nf = 0; nf < 8; nf++) {
            int c = colb + nf * 8;
            if (row_lo < n)
                *(float2*)(g_z + (size_t)row_lo * 128 + c) =
                    make_float2(acc[nf][0], acc[nf][1]);
            if (row_lo + 8 < n)
                *(float2*)(g_z + (size_t)(row_lo + 8) * 128 + c) =
                    make_float2(acc[nf][2], acc[nf][3]);
        }
    }
}

// ---------------------------------------------------------------------------
// Gather1 + fused GEMM2:
//   h2 = relu(mean_{s in nbr(i)} z[s] + b1) * mask[i]   (held in registers)
//   t[i] = h2 @ W2   (per-warp smem staging, 16 cols)
__global__ __launch_bounds__(256) void gather1_fused_kernel(
    const float* __restrict__ b1, const float* __restrict__ mask,
    const float* __restrict__ W2, int n) {
    __shared__ float W2s[128 * 16];
    __shared__ float h2s[8][128];

    // cooperative W2 load (before any early-out)
#pragma unroll
    for (int j = 0; j < 8; j++)
        W2s[threadIdx.x + j * 256] = W2[threadIdx.x + j * 256];
    __syncthreads();

    const int warp  = (blockIdx.x * blockDim.x + threadIdx.x) >> 5;
    const int lane  = threadIdx.x & 31;
    const int wslot = (threadIdx.x >> 5);
    if (warp >= n) return;

    const int deg = g_cnt[warp];
    const int d   = min(deg, CAP);
    const int* sl = g_slot + (size_t)warp * CAP;
    float4 acc = make_float4(0.f, 0.f, 0.f, 0.f);

    for (int base = 0; base < d; base += 32) {
        int nn = min(32, d - base);
        int my = (lane < nn) ? sl[base + lane] : 0;
        int e = 0;
        for (; e + 4 <= nn; e += 4) {   // 4-way MLP
            int s0 = __shfl_sync(0xffffffffu, my, e + 0);
            int s1 = __shfl_sync(0xffffffffu, my, e + 1);
            int s2 = __shfl_sync(0xffffffffu, my, e + 2);
            int s3 = __shfl_sync(0xffffffffu, my, e + 3);
            float4 v0 = *(const float4*)(g_z + (size_t)s0 * 128 + lane * 4);
            float4 v1 = *(const float4*)(g_z + (size_t)s1 * 128 + lane * 4);
            float4 v2 = *(const float4*)(g_z + (size_t)s2 * 128 + lane * 4);
            float4 v3 = *(const float4*)(g_z + (size_t)s3 * 128 + lane * 4);
            acc.x += v0.x + v1.x + v2.x + v3.x;
            acc.y += v0.y + v1.y + v2.y + v3.y;
            acc.z += v0.z + v1.z + v2.z + v3.z;
            acc.w += v0.w + v1.w + v2.w + v3.w;
        }
        for (; e < nn; e++) {
            int s = __shfl_sync(0xffffffffu, my, e);
            float4 v = *(const float4*)(g_z + (size_t)s * 128 + lane * 4);
            acc.x += v.x; acc.y += v.y; acc.z += v.z; acc.w += v.w;
        }
    }
    float scale = 1.f / (float)max(deg, 1);
    float bb0 = b1[lane * 4 + 0], bb1 = b1[lane * 4 + 1];
    float bb2 = b1[lane * 4 + 2], bb3 = b1[lane * 4 + 3];
    const float* mp = mask + (size_t)warp * 128 + lane * 4;
    float m0 = mp[0], m1 = mp[1], m2 = mp[2], m3 = mp[3];
    float4 r;
    r.x = fmaxf(fmaf(acc.x, scale, bb0), 0.f) * m0;
    r.y = fmaxf(fmaf(acc.y, scale, bb1), 0.f) * m1;
    r.z = fmaxf(fmaf(acc.z, scale, bb2), 0.f) * m2;
    r.w = fmaxf(fmaf(acc.w, scale, bb3), 0.f) * m3;

    // ---- fused gemm2: t[c] = sum_k h2[k] * W2[k][c] ----
    float* hb = h2s[wslot];
    *(float4*)(hb + lane * 4) = r;
    __syncwarp();

    const int c     = lane & 15;
    const int kbase = (lane >> 4) * 64;       // lanes 0-15: k 0..63; 16-31: 64..127
    float p = 0.f;
#pragma unroll 16
    for (int j = 0; j < 64; j++)
        p = fmaf(hb[kbase + j], W2s[(kbase + j) * 16 + c], p);
    p += __shfl_xor_sync(0xffffffffu, p, 16);
    if (lane < 16) g_t[(size_t)warp * 16 + c] = p;
}

// ---------------------------------------------------------------------------
// Gather2: out[i] = mean_{s in nbr(i)} t[s] + b2   (4 lanes per node)
__global__ __launch_bounds__(256) void gather2_kernel(
    const float* __restrict__ b2, float* __restrict__ out, int n) {
    const int gid  = blockIdx.x * blockDim.x + threadIdx.x;
    const int node = gid >> 2;
    const int q    = (gid & 3) * 4;
    if (node >= n) return;

    const int deg = g_cnt[node];
    const int d   = min(deg, CAP);
    const int* sl = g_slot + (size_t)node * CAP;
    float4 acc = make_float4(0.f, 0.f, 0.f, 0.f);

    int e = 0;
    for (; e + 4 <= d; e += 4) {
        int s0 = sl[e], s1 = sl[e + 1], s2 = sl[e + 2], s3 = sl[e + 3];
        float4 v0 = *(const float4*)(g_t + (size_t)s0 * 16 + q);
        float4 v1 = *(const float4*)(g_t + (size_t)s1 * 16 + q);
        float4 v2 = *(const float4*)(g_t + (size_t)s2 * 16 + q);
        float4 v3 = *(const float4*)(g_t + (size_t)s3 * 16 + q);
        acc.x += v0.x + v1.x + v2.x + v3.x;
        acc.y += v0.y + v1.y + v2.y + v3.y;
        acc.z += v0.z + v1.z + v2.z + v3.z;
        acc.w += v0.w + v1.w + v2.w + v3.w;
    }
    for (; e < d; e++) {
        int s = sl[e];
        float4 v = *(const float4*)(g_t + (size_t)s * 16 + q);
        acc.x += v.x; acc.y += v.y; acc.z += v.z; acc.w += v.w;
    }
    float scale = 1.f / (float)max(deg, 1);
    out[(size_t)node * 16 + q + 0] = fmaf(acc.x, scale, b2[q + 0]);
    out[(size_t)node * 16 + q + 1] = fmaf(acc.y, scale, b2[q + 1]);
    out[(size_t)node * 16 + q + 2] = fmaf(acc.z, scale, b2[q + 2]);
    out[(size_t)node * 16 + q + 3] = fmaf(acc.w, scale, b2[q + 3]);
}

// ---------------------------------------------------------------------------
extern "C" void kernel_launch(void* const* d_in, const int* in_sizes, int n_in,
                              void* d_out, int out_size) {
    const float* x    = (const float*)d_in[0];
    const void*  ei   = d_in[1];            // int32 or int64, probed on device
    const float* W1   = (const float*)d_in[2];
    const float* b1   = (const float*)d_in[3];
    const float* W2   = (const float*)d_in[4];
    const float* b2   = (const float*)d_in[5];
    const float* mask = (const float*)d_in[6];
    float*       out  = (float*)d_out;

    int n = in_sizes[0] / 128;
    if (n > MAXN) n = MAXN;
    int E = in_sizes[1] / 2;

    // idempotent; persists on the function after the first (pre-capture) call
    cudaFuncSetAttribute(gemm1_mma_kernel,
                         cudaFuncAttributeMaxDynamicSharedMemorySize,
                         G1_SMEM_TOTAL);

    zero_cnt_kernel<<<128, 512>>>(n);
    probe_kernel<<<1, 128>>>(ei, E, n);
    prep_w_kernel<<<64, 256>>>(W1);
    build_kernel<<<(E + 255) / 256, 256>>>(ei, E, n);
    gemm1_mma_kernel<<<(n + 127) / 128, 512, G1_SMEM_TOTAL>>>(x, n);
    gather1_fused_kernel<<<(n + 7) / 8, 256>>>(b1, mask, W2, n);
    gather2_kernel<<<(4 * n + 255) / 256, 256>>>(b2, out, n);
}

// round 13
// speedup vs baseline: 1.1843x; 1.0373x over previous
#include <cuda_runtime.h>
#include <cuda_bf16.h>
#include <cstdint>

// Problem constants (fixed by the dataset)
#define MAXN 50000
#define CAP  128      // max in-degree capacity (Poisson(16): P(deg>=128) ~ 0)

// Scratch (device globals: allocation-free per harness rules)
__device__ __align__(128) int   g_cnt[MAXN];                // in-degree
__device__ __align__(128) int   g_slot[(size_t)MAXN * CAP]; // bucketed src per dst
__device__ __align__(128) float g_z  [(size_t)MAXN * 128];  // z  = x @ W1
__device__ __align__(128) float g_t  [(size_t)MAXN * 16];   // t  = h2 @ W2
__device__ __align__(128) __nv_bfloat16 g_wh[128 * 128];    // W1^T hi  [nc][k]
__device__ __align__(128) __nv_bfloat16 g_wl[128 * 128];    // W1^T lo  [nc][k]
__device__ int g_is64;                                      // edge dtype flag

// ---------------------------------------------------------------------------
__device__ __forceinline__ uint32_t smem_to_u32(const void* p) {
    uint32_t a;
    asm("{ .reg .u64 t; cvta.to.shared.u64 t, %1; cvt.u32.u64 %0, t; }"
        : "=r"(a) : "l"(p));
    return a;
}

// Portable tensor-core primitives (sm_80+; valid on base compute_103 target)
#define LDSM_X4(r, addr) \
    asm volatile("ldmatrix.sync.aligned.m8n8.x4.shared.b16 {%0,%1,%2,%3}, [%4];" \
        : "=r"((r)[0]), "=r"((r)[1]), "=r"((r)[2]), "=r"((r)[3]) : "r"(addr))

#define MMA_BF16(d, a, b) \
    asm volatile("mma.sync.aligned.m16n8k16.row.col.f32.bf16.bf16.f32 " \
        "{%0,%1,%2,%3}, {%4,%5,%6,%7}, {%8,%9}, {%0,%1,%2,%3};" \
        : "+f"((d)[0]), "+f"((d)[1]), "+f"((d)[2]), "+f"((d)[3]) \
        : "r"((a)[0]), "r"((a)[1]), "r"((a)[2]), "r"((a)[3]), \
          "r"((b)[0]), "r"((b)[1]))

// ---------------------------------------------------------------------------
// Setup: zero g_cnt, split W1 -> g_wh/g_wl, probe edge dtype (block 0, ordered)
__global__ void setup_kernel(const float* __restrict__ W,
                             const void* __restrict__ ei, int E, int n) {
    const int tid = threadIdx.x;
    const int gid = blockIdx.x * blockDim.x + tid;

    if (blockIdx.x == 0) {
        if (tid == 0) g_is64 = 1;
        __syncthreads();
        const long long* e64 = (const long long*)ei;
        int m = min(128, E);
        if (tid < m) {
            long long v = e64[tid];   // within allocation for either dtype
            if (v < 0 || v >= (long long)n) atomicAnd(&g_is64, 0);
        }
    }
    // zero in-degree counters
    for (int i = gid; i < n; i += gridDim.x * blockDim.x)
        g_cnt[i] = 0;
    // W1 split: g_wh/g_wl[nc][k] = split_bf16(W1[k][nc])
    for (int i = gid; i < 128 * 128; i += gridDim.x * blockDim.x) {
        int nc = i & 127;
        float f = W[i];                      // W[k*128 + nc], coalesced
        __nv_bfloat16 h = __float2bfloat16(f);
        g_wh[nc * 128 + (i >> 7)] = h;
        g_wl[nc * 128 + (i >> 7)] = __float2bfloat16(f - __bfloat162float(h));
    }
}

// ============================================================================
// GEMM1 (HMMA) + fused edge-build prologue.
//   Build: each block handles ~E/nb edges (atomicAdd placement into g_slot);
//   independent of the GEMM, hidden under staging + MMA latency.
//   GEMM: g_z[N,128] = X[N,128] @ W1[128,128], split-bf16 (3 products).
//   Block: 512 threads / 16 warps, tile 128 rows x 128 cols.
//   smem rows stride XS=136 bf16 (272B == 16 mod 128: ldmatrix conflict-free).
// ============================================================================
#define XS 136
#define TILE_ELEMS (128 * XS)
#define G1_SMEM_TOTAL (4 * TILE_ELEMS * 2)   // Xh, Xl, Bh, Bl = 139264 B

__global__ void __launch_bounds__(512, 1)
gemm1_build_kernel(const float* __restrict__ X,
                   const void* __restrict__ ei, int E, int n) {
    extern __shared__ __align__(16) char smem_raw[];
    __nv_bfloat16* Xh = (__nv_bfloat16*)smem_raw;       // [128][XS] row=m, col=k
    __nv_bfloat16* Xl = Xh + TILE_ELEMS;
    __nv_bfloat16* Bh = Xl + TILE_ELEMS;                // [128][XS] row=n, col=k
    __nv_bfloat16* Bl = Bh + TILE_ELEMS;

    const int tid  = threadIdx.x;
    const int wid  = tid >> 5;
    const int lane = tid & 31;
    const int row0 = blockIdx.x * 128;

    // ---- build prologue: this block's edge chunk (independent of GEMM) ----
    {
        const int nb  = gridDim.x;
        const int per = (E + nb - 1) / nb;
        const int e0  = blockIdx.x * per;
        const int e1  = min(E, e0 + per);
        const int isw = g_is64;
        for (int e = e0 + tid; e < e1; e += 512) {
            int s, d;
            if (isw) {
                const long long* e64 = (const long long*)ei;
                s = (int)e64[e];
                d = (int)e64[(size_t)E + e];
            } else {
                const int* e32 = (const int*)ei;
                s = e32[e];
                d = e32[(size_t)E + e];
            }
            if (d >= 0 && d < n && s >= 0 && s < n) {
                int pos = atomicAdd(&g_cnt[d], 1);
                if (pos < CAP) g_slot[(size_t)d * CAP + pos] = s;
            }
        }
    }

    // ---- stage + split-convert X tile: thread -> (row, k-quarter) ----
    {
        const int r = tid >> 2, q = tid & 3;
        int gr = row0 + r; if (gr >= n) gr = n - 1;   // clamp; stores guarded later
        const float* xp = X + (size_t)gr * 128 + q * 32;
        __nv_bfloat16* ph = Xh + r * XS + q * 32;
        __nv_bfloat16* pl = Xl + r * XS + q * 32;
#pragma unroll
        for (int j = 0; j < 32; j += 4) {
            float4 v = *(const float4*)(xp + j);
            float fv[4] = {v.x, v.y, v.z, v.w};
#pragma unroll
            for (int e = 0; e < 4; e++) {
                __nv_bfloat16 h = __float2bfloat16(fv[e]);
                __nv_bfloat16 l = __float2bfloat16(fv[e] - __bfloat162float(h));
                ph[j + e] = h;
                pl[j + e] = l;
            }
        }
    }
    // ---- stage B tiles: straight uint4 copy from pre-split g_wh/g_wl ----
    {
#pragma unroll
        for (int it = 0; it < 4; it++) {
            int idx = tid + it * 512;          // 0..2047 : row = idx>>4, 16B chunk
            int row = idx >> 4, c16 = idx & 15;
            ((uint4*)(Bh + row * XS))[c16] = ((const uint4*)(g_wh + row * 128))[c16];
            ((uint4*)(Bl + row * XS))[c16] = ((const uint4*)(g_wl + row * 128))[c16];
        }
    }
    __syncthreads();

    // ---- warp tile: rows strip rs = (wid>>1)*16, col half ch = wid&1 ----
    const int rs = (wid >> 1) * 16;
    const int ch = wid & 1;

    float acc[8][4];
#pragma unroll
    for (int nf = 0; nf < 8; nf++)
#pragma unroll
        for (int c = 0; c < 4; c++) acc[nf][c] = 0.f;

    const int a_row  = rs + ((lane >> 3) & 1) * 8 + (lane & 7);
    const int a_koff = (lane >> 4) * 8;
    const uint32_t a_hi_base = smem_to_u32(Xh + a_row * XS + a_koff);
    const uint32_t a_lo_base = smem_to_u32(Xl + a_row * XS + a_koff);

    // Fused B ldmatrix.x4: lanes 0-15 -> Bh (k0/k8), lanes 16-31 -> Bl.
    {
        const __nv_bfloat16* barr = (lane & 16) ? Bl : Bh;
        const int b_row  = ch * 64 + (lane & 7);
        const int b_koff = ((lane >> 3) & 1) * 8;
        const uint32_t b_base = smem_to_u32(barr + b_row * XS + b_koff);

#pragma unroll
        for (int k = 0; k < 8; k++) {
            uint32_t ah[4], al[4];
            LDSM_X4(ah, a_hi_base + k * 32);   // 16 bf16 = 32B per k-step
            LDSM_X4(al, a_lo_base + k * 32);
#pragma unroll
            for (int nf = 0; nf < 8; nf++) {
                uint32_t bb[4];
                LDSM_X4(bb, b_base + nf * (8 * XS * 2) + k * 32);
                MMA_BF16(acc[nf], ah, bb + 0);   // Ah * Bh
                MMA_BF16(acc[nf], ah, bb + 2);   // Ah * Bl
                MMA_BF16(acc[nf], al, bb + 0);   // Al * Bh
            }
        }
    }

    // ---- epilogue: c0,c1 -> (row, col..col+1); c2,c3 -> (row+8, ..) ----
    {
        const int row_lo = row0 + rs + (lane >> 2);
        const int colb   = ch * 64 + (lane & 3) * 2;
#pragma unroll
        for (int nf = 0; nf < 8; nf++) {
            int c = colb + nf * 8;
            if (row_lo < n)
                *(float2*)(g_z + (size_t)row_lo * 128 + c) =
                    make_float2(acc[nf][0], acc[nf][1]);
            if (row_lo + 8 < n)
                *(float2*)(g_z + (size_t)(row_lo + 8) * 128 + c) =
                    make_float2(acc[nf][2], acc[nf][3]);
        }
    }
}

// ---------------------------------------------------------------------------
// Gather1 + fused GEMM2:
//   h2 = relu(mean_{s in nbr(i)} z[s] + b1) * mask[i]   (held in registers)
//   t[i] = h2 @ W2   (per-warp smem staging, 16 cols)
__global__ __launch_bounds__(256) void gather1_fused_kernel(
    const float* __restrict__ b1, const float* __restrict__ mask,
    const float* __restrict__ W2, int n) {
    __shared__ float W2s[128 * 16];
    __shared__ float h2s[8][128];

    // cooperative W2 load (before any early-out)
#pragma unroll
    for (int j = 0; j < 8; j++)
        W2s[threadIdx.x + j * 256] = W2[threadIdx.x + j * 256];
    __syncthreads();

    const int warp  = (blockIdx.x * blockDim.x + threadIdx.x) >> 5;
    const int lane  = threadIdx.x & 31;
    const int wslot = (threadIdx.x >> 5);
    if (warp >= n) return;

    const int deg = g_cnt[warp];
    const int d   = min(deg, CAP);
    const int* sl = g_slot + (size_t)warp * CAP;
    float4 acc = make_float4(0.f, 0.f, 0.f, 0.f);

    for (int base = 0; base < d; base += 32) {
        int nn = min(32, d - base);
        int my = (lane < nn) ? sl[base + lane] : 0;
        int e = 0;
        for (; e + 4 <= nn; e += 4) {   // 4-way MLP
            int s0 = __shfl_sync(0xffffffffu, my, e + 0);
            int s1 = __shfl_sync(0xffffffffu, my, e + 1);
            int s2 = __shfl_sync(0xffffffffu, my, e + 2);
            int s3 = __shfl_sync(0xffffffffu, my, e + 3);
            float4 v0 = *(const float4*)(g_z + (size_t)s0 * 128 + lane * 4);
            float4 v1 = *(const float4*)(g_z + (size_t)s1 * 128 + lane * 4);
            float4 v2 = *(const float4*)(g_z + (size_t)s2 * 128 + lane * 4);
            float4 v3 = *(const float4*)(g_z + (size_t)s3 * 128 + lane * 4);
            acc.x += v0.x + v1.x + v2.x + v3.x;
            acc.y += v0.y + v1.y + v2.y + v3.y;
            acc.z += v0.z + v1.z + v2.z + v3.z;
            acc.w += v0.w + v1.w + v2.w + v3.w;
        }
        for (; e < nn; e++) {
            int s = __shfl_sync(0xffffffffu, my, e);
            float4 v = *(const float4*)(g_z + (size_t)s * 128 + lane * 4);
            acc.x += v.x; acc.y += v.y; acc.z += v.z; acc.w += v.w;
        }
    }
    float scale = 1.f / (float)max(deg, 1);
    float bb0 = b1[lane * 4 + 0], bb1 = b1[lane * 4 + 1];
    float bb2 = b1[lane * 4 + 2], bb3 = b1[lane * 4 + 3];
    const float* mp = mask + (size_t)warp * 128 + lane * 4;
    float m0 = mp[0], m1 = mp[1], m2 = mp[2], m3 = mp[3];
    float4 r;
    r.x = fmaxf(fmaf(acc.x, scale, bb0), 0.f) * m0;
    r.y = fmaxf(fmaf(acc.y, scale, bb1), 0.f) * m1;
    r.z = fmaxf(fmaf(acc.z, scale, bb2), 0.f) * m2;
    r.w = fmaxf(fmaf(acc.w, scale, bb3), 0.f) * m3;

    // ---- fused gemm2: t[c] = sum_k h2[k] * W2[k][c] ----
    float* hb = h2s[wslot];
    *(float4*)(hb + lane * 4) = r;
    __syncwarp();

    const int c     = lane & 15;
    const int kbase = (lane >> 4) * 64;       // lanes 0-15: k 0..63; 16-31: 64..127
    float p = 0.f;
#pragma unroll 16
    for (int j = 0; j < 64; j++)
        p = fmaf(hb[kbase + j], W2s[(kbase + j) * 16 + c], p);
    p += __shfl_xor_sync(0xffffffffu, p, 16);
    if (lane < 16) g_t[(size_t)warp * 16 + c] = p;
}

// ---------------------------------------------------------------------------
// Gather2: out[i] = mean_{s in nbr(i)} t[s] + b2   (4 lanes per node)
__global__ __launch_bounds__(256) void gather2_kernel(
    const float* __restrict__ b2, float* __restrict__ out, int n) {
    const int gid  = blockIdx.x * blockDim.x + threadIdx.x;
    const int node = gid >> 2;
    const int q    = (gid & 3) * 4;
    if (node >= n) return;

    const int deg = g_cnt[node];
    const int d   = min(deg, CAP);
    const int* sl = g_slot + (size_t)node * CAP;
    float4 acc = make_float4(0.f, 0.f, 0.f, 0.f);

    int e = 0;
    for (; e + 4 <= d; e += 4) {
        int s0 = sl[e], s1 = sl[e + 1], s2 = sl[e + 2], s3 = sl[e + 3];
        float4 v0 = *(const float4*)(g_t + (size_t)s0 * 16 + q);
        float4 v1 = *(const float4*)(g_t + (size_t)s1 * 16 + q);
        float4 v2 = *(const float4*)(g_t + (size_t)s2 * 16 + q);
        float4 v3 = *(const float4*)(g_t + (size_t)s3 * 16 + q);
        acc.x += v0.x + v1.x + v2.x + v3.x;
        acc.y += v0.y + v1.y + v2.y + v3.y;
        acc.z += v0.z + v1.z + v2.z + v3.z;
        acc.w += v0.w + v1.w + v2.w + v3.w;
    }
    for (; e < d; e++) {
        int s = sl[e];
        float4 v = *(const float4*)(g_t + (size_t)s * 16 + q);
        acc.x += v.x; acc.y += v.y; acc.z += v.z; acc.w += v.w;
    }
    float scale = 1.f / (float)max(deg, 1);
    out[(size_t)node * 16 + q + 0] = fmaf(acc.x, scale, b2[q + 0]);
    out[(size_t)node * 16 + q + 1] = fmaf(acc.y, scale, b2[q + 1]);
    out[(size_t)node * 16 + q + 2] = fmaf(acc.z, scale, b2[q + 2]);
    out[(size_t)node * 16 + q + 3] = fmaf(acc.w, scale, b2[q + 3]);
}

// ---------------------------------------------------------------------------
extern "C" void kernel_launch(void* const* d_in, const int* in_sizes, int n_in,
                              void* d_out, int out_size) {
    const float* x    = (const float*)d_in[0];
    const void*  ei   = d_in[1];            // int32 or int64, probed on device
    const float* W1   = (const float*)d_in[2];
    const float* b1   = (const float*)d_in[3];
    const float* W2   = (const float*)d_in[4];
    const float* b2   = (const float*)d_in[5];
    const float* mask = (const float*)d_in[6];
    float*       out  = (float*)d_out;

    int n = in_sizes[0] / 128;
    if (n > MAXN) n = MAXN;
    int E = in_sizes[1] / 2;

    // idempotent; persists on the function after the first (pre-capture) call
    cudaFuncSetAttribute(gemm1_build_kernel,
                         cudaFuncAttributeMaxDynamicSharedMemorySize,
                         G1_SMEM_TOTAL);

    setup_kernel<<<196, 256>>>(W1, ei, E, n);
    gemm1_build_kernel<<<(n + 127) / 128, 512, G1_SMEM_TOTAL>>>(x, ei, E, n);
    gather1_fused_kernel<<<(n + 7) / 8, 256>>>(b1, mask, W2, n);
    gather2_kernel<<<(4 * n + 255) / 256, 256>>>(b2, out, n);
}